// round 8
// baseline (speedup 1.0000x reference)
#include <cuda_runtime.h>
#include <cstdint>

// Problem constants
#define NN   512
#define NIN  6
#define NOUT 2
#define TS   1200
#define NB   128
#define TB   (TS * NB)          // 153600

// Decomposition: 16 batch-groups x (cluster of 8 n-slice CTAs) = 128 CTAs
#define NSL     8               // n-slices (cluster size)
#define ROWS    64              // rows of W_rec per CTA
#define NBG     16              // batch groups
#define BG      8               // batch per group
#define THREADS 256
#define NSEG    16              // k-segments (8 warps x 2 half-warps)
#define BP      12              // partials row pad (floats, mult of 4 for STS.128)

#define F_SSH   ((NN + NIN + 2) * BG)   // 4160: 512 state rows + 6 input rows + pad
#define F_PART  (NSEG * ROWS * BP)      // 12288
#define SMEM_FLOATS (F_SSH + F_PART)
#define SMEM_BYTES  (SMEM_FLOATS * 4)   // 65792 B

// Ping-pong state exchange buffer (per batch-group), lives in L2.
__device__ float g_S[2][NBG][NN][BG];

typedef unsigned long long ull;

__device__ __forceinline__ ull pack2(float x) {
    ull r;
    unsigned int v = __float_as_uint(x);
    asm("mov.b64 %0, {%1, %1};" : "=l"(r) : "r"(v));
    return r;
}
__device__ __forceinline__ void fma2(ull& d, ull a, ull b) {
    asm("fma.rn.f32x2 %0, %1, %2, %0;" : "+l"(d) : "l"(a), "l"(b));
}
__device__ __forceinline__ void unpack2(ull v, float& lo, float& hi) {
    unsigned int l, h;
    asm("mov.b64 {%0, %1}, %2;" : "=r"(l), "=r"(h) : "l"(v));
    lo = __uint_as_float(l);
    hi = __uint_as_float(h);
}
__device__ __forceinline__ float tanh_fast(float x) {
    float r;
    asm("tanh.approx.f32 %0, %1;" : "=f"(r) : "f"(x));
    return r;
}
__device__ __forceinline__ void cluster_arrive_() {
    asm volatile("barrier.cluster.arrive.aligned;" ::: "memory");
}
__device__ __forceinline__ void cluster_wait_() {
    asm volatile("barrier.cluster.wait.aligned;" ::: "memory");
}

// One FFMA2 quad: 1 weight value against 8 batches (4 f32x2 pairs)
#define QFMA(ar, wv, sA, sB)                 \
    do {                                      \
        ull _w = pack2(wv);                   \
        fma2(ar##0, _w, sA.x);                \
        fma2(ar##1, _w, sA.y);                \
        fma2(ar##2, _w, sB.x);                \
        fma2(ar##3, _w, sB.y);                \
    } while (0)

extern "C" __global__ void __cluster_dims__(NSL, 1, 1) __launch_bounds__(THREADS, 1)
rnn_step_kernel(const float* __restrict__ u,
                const float* __restrict__ Wrec,
                const float* __restrict__ Winp,
                const float* __restrict__ Wout,
                const float* __restrict__ y_init,
                const float* __restrict__ rnoise,
                const float* __restrict__ inoise,
                float* __restrict__ states,
                float* __restrict__ outs)
{
    extern __shared__ float sm[];
    float* s_sh = sm;                // [520][8] rows 0..511 state, 512..517 = u+inoise
    float* part = s_sh + F_SSH;      // [16 seg][64 n][12]

    const int tid  = threadIdx.x;
    const int ns   = blockIdx.x;     // cluster rank / n-slice
    const int bg   = blockIdx.y;     // batch group
    const int n0   = ns * ROWS;
    const int b0   = bg * BG;
    const int lane = tid & 31;
    const int wid  = tid >> 5;       // 0..7
    const int g    = lane & 15;      // row group: rows {2g,2g+1,2g+32,2g+33}
    const int h    = lane >> 4;      // k half within warp's 64-k segment
    const int seg  = wid * 2 + h;    // 0..15
    const int kb   = wid * 64 + h * 32;   // this thread's k base

    const int r0 = 2 * g, r1 = 2 * g + 1, r2 = 2 * g + 32, r3 = 2 * g + 33;

    // ---- W_rec slice into registers: 4 rows x 32 k = 32 float4 ----
    float4 wr0[8], wr1[8], wr2[8], wr3[8];
    {
        const float* p0 = Wrec + (size_t)(n0 + r0) * NN + kb;
        const float* p1 = Wrec + (size_t)(n0 + r1) * NN + kb;
        const float* p2 = Wrec + (size_t)(n0 + r2) * NN + kb;
        const float* p3 = Wrec + (size_t)(n0 + r3) * NN + kb;
        #pragma unroll
        for (int q = 0; q < 8; ++q) {
            wr0[q] = *(const float4*)(p0 + 4 * q);
            wr1[q] = *(const float4*)(p1 + 4 * q);
            wr2[q] = *(const float4*)(p2 + 4 * q);
            wr3[q] = *(const float4*)(p3 + 4 * q);
        }
    }
    // Input-term weights (k-row 512+seg), only segs 0..5 active
    float wi0 = 0.f, wi1 = 0.f, wi2 = 0.f, wi3 = 0.f;
    if (seg < NIN) {
        wi0 = Winp[(size_t)(n0 + r0) * NIN + seg];
        wi1 = Winp[(size_t)(n0 + r1) * NIN + seg];
        wi2 = Winp[(size_t)(n0 + r2) * NIN + seg];
        wi3 = Winp[(size_t)(n0 + r3) * NIN + seg];
    }

    // Reducer output assignments (2 outputs per thread)
    const int n_r0 = tid >> 3;            // 0..31
    const int n_r1 = (tid + 256) >> 3;    // 32..63
    const int b_r  = tid & 7;
    // W_out weights for this thread's 2 rows
    const float wo0a = Wout[n0 + n_r0];
    const float wo0b = Wout[n0 + n_r1];
    const float wo1a = Wout[NN + n0 + n_r0];
    const float wo1b = Wout[NN + n0 + n_r1];

    // x loader assignment (threads 0..47)
    const bool xload = (tid < NIN * BG);
    const int  xi = tid >> 3, xb = tid & 7;

    // ---- Init state buffer + states[:,0,:] ----
    for (int idx = tid; idx < ROWS * BG; idx += THREADS) {
        int k = n0 + (idx >> 3);
        int b = idx & 7;
        float v = y_init[k];
        g_S[0][bg][k][b] = v;
        states[(size_t)k * TB + b0 + b] = v;
    }
    // ---- rank 0 zeroes this batch-group's output slab ----
    if (ns == 0) {
        for (int idx = tid; idx < NOUT * TS * BG; idx += THREADS) {
            int o   = idx / (TS * BG);          // 0 or 1 (stride 9600, NOT a shift)
            int rem = idx - o * TS * BG;
            int t = rem >> 3;
            int b = rem & 7;
            outs[(size_t)o * TB + (size_t)t * NB + b0 + b] = 0.f;
        }
    }
    __syncthreads();
    cluster_arrive_();

    // ---- Prefetch t=0 streamed operands ----
    float x_v = 0.f, rn0, rn1;
    if (xload) {
        size_t off = (size_t)xi * TB + b0 + xb;
        x_v = __ldcs(u + off) + __ldcs(inoise + off);
    }
    rn0 = __ldcs(rnoise + (size_t)(n0 + n_r0) * TB + b0 + b_r);
    rn1 = __ldcs(rnoise + (size_t)(n0 + n_r1) * TB + b0 + b_r);

    cluster_wait_();   // g_S init + output zeroing visible cluster-wide

    // ---- t = 0 outputs: Wout @ s0 (REDG accumulate) ----
    {
        float s0v = y_init[n0 + n_r0];
        float s1v = y_init[n0 + n_r1];
        float v0 = wo0a * s0v + wo0b * s1v;
        float v1 = wo1a * s0v + wo1b * s1v;
        v0 += __shfl_xor_sync(0xffffffffu, v0, 8);
        v0 += __shfl_xor_sync(0xffffffffu, v0, 16);
        v1 += __shfl_xor_sync(0xffffffffu, v1, 8);
        v1 += __shfl_xor_sync(0xffffffffu, v1, 16);
        if (lane < 8) {
            atomicAdd(outs + b0 + lane, v0);
            atomicAdd(outs + TB + b0 + lane, v1);
        }
    }

    const float* sbase = s_sh + kb * BG;
    const float* sext  = s_sh + (NN + seg) * BG;

    for (int t = 0; t < TS - 1; ++t) {
        // ---- 1. stage full state (16KB) from L2 into s_sh ----
        const float4* Sp = (const float4*)(&g_S[t & 1][bg][0][0]);
        float4 v0 = __ldcg(Sp + tid);
        float4 v1 = __ldcg(Sp + tid + 256);
        float4 v2 = __ldcg(Sp + tid + 512);
        float4 v3 = __ldcg(Sp + tid + 768);
        float4* s4 = (float4*)s_sh;
        s4[tid]       = v0;
        s4[tid + 256] = v1;
        s4[tid + 512] = v2;
        s4[tid + 768] = v3;
        if (xload) s_sh[(NN + xi) * BG + xb] = x_v;
        __syncthreads();

        // ---- 2. GEMM partials: 32 k's (regs W) x 4 rows x 8 batches ----
        ull a00 = 0, a01 = 0, a02 = 0, a03 = 0;
        ull a10 = 0, a11 = 0, a12 = 0, a13 = 0;
        ull a20 = 0, a21 = 0, a22 = 0, a23 = 0;
        ull a30 = 0, a31 = 0, a32 = 0, a33 = 0;
        {
            const float* sp = sbase;
            #pragma unroll
            for (int q = 0; q < 8; ++q) {
                float4 w0q = wr0[q], w1q = wr1[q], w2q = wr2[q], w3q = wr3[q];
                #pragma unroll
                for (int c = 0; c < 4; ++c) {
                    ulonglong2 sA = *(const ulonglong2*)(sp);
                    ulonglong2 sB = *(const ulonglong2*)(sp + 4);
                    float w0v = (c == 0) ? w0q.x : (c == 1) ? w0q.y : (c == 2) ? w0q.z : w0q.w;
                    float w1v = (c == 0) ? w1q.x : (c == 1) ? w1q.y : (c == 2) ? w1q.z : w1q.w;
                    float w2v = (c == 0) ? w2q.x : (c == 1) ? w2q.y : (c == 2) ? w2q.z : w2q.w;
                    float w3v = (c == 0) ? w3q.x : (c == 1) ? w3q.y : (c == 2) ? w3q.z : w3q.w;
                    QFMA(a0, w0v, sA, sB);
                    QFMA(a1, w1v, sA, sB);
                    QFMA(a2, w2v, sA, sB);
                    QFMA(a3, w3v, sA, sB);
                    sp += BG;
                }
            }
            if (seg < NIN) {   // fold input term: one extra k-row (512+seg)
                ulonglong2 sA = *(const ulonglong2*)(sext);
                ulonglong2 sB = *(const ulonglong2*)(sext + 4);
                QFMA(a0, wi0, sA, sB);
                QFMA(a1, wi1, sA, sB);
                QFMA(a2, wi2, sA, sB);
                QFMA(a3, wi3, sA, sB);
            }
        }
        // ---- 3. store partials: per row, 8 floats (b0..b7) as 2x STS.128 ----
        {
            float4 q;
            float* pb = part + (seg * ROWS) * BP;
            unpack2(a00, q.x, q.y); unpack2(a01, q.z, q.w);
            *(float4*)(pb + r0 * BP) = q;
            unpack2(a02, q.x, q.y); unpack2(a03, q.z, q.w);
            *(float4*)(pb + r0 * BP + 4) = q;
            unpack2(a10, q.x, q.y); unpack2(a11, q.z, q.w);
            *(float4*)(pb + r1 * BP) = q;
            unpack2(a12, q.x, q.y); unpack2(a13, q.z, q.w);
            *(float4*)(pb + r1 * BP + 4) = q;
            unpack2(a20, q.x, q.y); unpack2(a21, q.z, q.w);
            *(float4*)(pb + r2 * BP) = q;
            unpack2(a22, q.x, q.y); unpack2(a23, q.z, q.w);
            *(float4*)(pb + r2 * BP + 4) = q;
            unpack2(a30, q.x, q.y); unpack2(a31, q.z, q.w);
            *(float4*)(pb + r3 * BP) = q;
            unpack2(a32, q.x, q.y); unpack2(a33, q.z, q.w);
            *(float4*)(pb + r3 * BP + 4) = q;
        }
        __syncthreads();

        // ---- 4. reduce 16 partials, tanh, update, fused W_out REDG ----
        {
            float pre0 = 0.f, pre1 = 0.f;
            #pragma unroll
            for (int sp = 0; sp < NSEG; ++sp) {
                pre0 += part[(sp * ROWS + n_r0) * BP + b_r];
                pre1 += part[(sp * ROWS + n_r1) * BP + b_r];
            }
            float s0 = s_sh[(n0 + n_r0) * BG + b_r];
            float s1 = s_sh[(n0 + n_r1) * BG + b_r];
            float ns0 = 0.9f * s0 + 0.1f * (tanh_fast(pre0) + rn0);
            float ns1 = 0.9f * s1 + 0.1f * (tanh_fast(pre1) + rn1);
            float* Sn = &g_S[(t + 1) & 1][bg][0][0];
            Sn[(n0 + n_r0) * BG + b_r] = ns0;
            Sn[(n0 + n_r1) * BG + b_r] = ns1;
            size_t so = (size_t)(t + 1) * NB + b0 + b_r;
            states[(size_t)(n0 + n_r0) * TB + so] = ns0;
            states[(size_t)(n0 + n_r1) * TB + so] = ns1;

            // fused output: outs[o][t+1][b] += sum_n Wout[o][n]*ns
            float v0 = wo0a * ns0 + wo0b * ns1;
            float v1 = wo1a * ns0 + wo1b * ns1;
            v0 += __shfl_xor_sync(0xffffffffu, v0, 8);
            v0 += __shfl_xor_sync(0xffffffffu, v0, 16);
            v1 += __shfl_xor_sync(0xffffffffu, v1, 8);
            v1 += __shfl_xor_sync(0xffffffffu, v1, 16);
            if (lane < 8) {
                size_t oc = (size_t)(t + 1) * NB + b0 + lane;
                atomicAdd(outs + oc, v0);
                atomicAdd(outs + TB + oc, v1);
            }
        }
        cluster_arrive_();

        // ---- 5. prefetch next step's streamed operands under the barrier ----
        if (t + 1 < TS - 1) {
            size_t toff = (size_t)(t + 1) * NB + b0;
            if (xload) {
                size_t off = (size_t)xi * TB + toff + xb;
                x_v = __ldcs(u + off) + __ldcs(inoise + off);
            }
            rn0 = __ldcs(rnoise + (size_t)(n0 + n_r0) * TB + toff + b_r);
            rn1 = __ldcs(rnoise + (size_t)(n0 + n_r1) * TB + toff + b_r);
        }
        cluster_wait_();
    }
}

extern "C" void kernel_launch(void* const* d_in, const int* in_sizes, int n_in,
                              void* d_out, int out_size)
{
    const float* u      = (const float*)d_in[0];
    const float* Wrec   = (const float*)d_in[1];
    const float* Winp   = (const float*)d_in[2];
    const float* Wout   = (const float*)d_in[3];
    const float* y_init = (const float*)d_in[4];
    const float* rnoise = (const float*)d_in[5];
    const float* inoise = (const float*)d_in[6];

    float* states = (float*)d_out;
    float* outs   = states + (size_t)NN * TB;

    cudaFuncSetAttribute(rnn_step_kernel,
                         cudaFuncAttributeMaxDynamicSharedMemorySize, SMEM_BYTES);

    dim3 grid(NSL, NBG, 1);
    rnn_step_kernel<<<grid, THREADS, SMEM_BYTES>>>(u, Wrec, Winp, Wout, y_init,
                                                   rnoise, inoise, states, outs);
}

// round 9
// speedup vs baseline: 1.0848x; 1.0848x over previous
#include <cuda_runtime.h>
#include <cstdint>

// Problem constants
#define NN   512
#define NIN  6
#define NOUT 2
#define TS   1200
#define NB   128
#define TB   (TS * NB)          // 153600

// Decomposition: 16 batch-groups x (cluster of 8 n-slice CTAs) = 128 CTAs
#define NSL     8               // n-slices (cluster size)
#define ROWS    64              // rows of W_rec per CTA
#define NBG     16              // batch groups
#define BG      8               // batch per group
#define THREADS 256
#define NSEG    16              // k-segments (8 warps x 2 half-warps)
#define BP      12              // partials row pad (floats, mult of 4 for STS.128)

#define F_SSH   ((NN + NIN + 2) * BG)   // 4160: 512 state rows + 6 input rows + pad
#define F_PART  (NSEG * ROWS * BP)      // 12288
#define F_MBAR  4                       // 2 x 8-byte mbarriers
#define SMEM_FLOATS (F_SSH + F_PART + F_MBAR)
#define SMEM_BYTES  (SMEM_FLOATS * 4)   // 65808 B

#define MBAR_ARRIVALS (8 * NSL)         // 8 warp-leaders per CTA x 8 CTAs = 64

// Ping-pong state exchange buffer (per batch-group), lives in L2.
__device__ float g_S[2][NBG][NN][BG];

typedef unsigned long long ull;

__device__ __forceinline__ ull pack2(float x) {
    ull r;
    unsigned int v = __float_as_uint(x);
    asm("mov.b64 %0, {%1, %1};" : "=l"(r) : "r"(v));
    return r;
}
__device__ __forceinline__ void fma2(ull& d, ull a, ull b) {
    asm("fma.rn.f32x2 %0, %1, %2, %0;" : "+l"(d) : "l"(a), "l"(b));
}
__device__ __forceinline__ void unpack2(ull v, float& lo, float& hi) {
    unsigned int l, h;
    asm("mov.b64 {%0, %1}, %2;" : "=r"(l), "=r"(h) : "l"(v));
    lo = __uint_as_float(l);
    hi = __uint_as_float(h);
}
__device__ __forceinline__ float tanh_fast(float x) {
    float r;
    asm("tanh.approx.f32 %0, %1;" : "=f"(r) : "f"(x));
    return r;
}
__device__ __forceinline__ uint32_t smem_u32(const void* p) {
    uint32_t a;
    asm("{ .reg .u64 t; cvta.to.shared.u64 t, %1; cvt.u32.u64 %0, t; }"
        : "=r"(a) : "l"(p));
    return a;
}
__device__ __forceinline__ void mbar_init(uint32_t addr, uint32_t cnt) {
    asm volatile("mbarrier.init.shared.b64 [%0], %1;" :: "r"(addr), "r"(cnt) : "memory");
}
__device__ __forceinline__ void fence_cluster_() {
    asm volatile("fence.acq_rel.cluster;" ::: "memory");
}
// Arrive on cluster CTA `rank`'s mbarrier at the same smem offset.
__device__ __forceinline__ void mbar_arrive_rank(uint32_t addr, uint32_t rank) {
    asm volatile(
        "{\n\t"
        ".reg .b32 ra;\n\t"
        "mapa.shared::cluster.u32 ra, %0, %1;\n\t"
        "mbarrier.arrive.shared::cluster.b64 _, [ra];\n\t"
        "}"
        :: "r"(addr), "r"(rank) : "memory");
}
// Spin-wait on local mbarrier phase parity with cluster-scope acquire.
__device__ __forceinline__ void mbar_wait_cluster(uint32_t mbar, uint32_t par) {
    uint32_t done;
    asm volatile(
        "{\n\t"
        ".reg .pred p;\n\t"
        "mbarrier.try_wait.parity.acquire.cluster.shared::cta.b64 p, [%1], %2;\n\t"
        "selp.b32 %0, 1, 0, p;\n\t"
        "}"
        : "=r"(done) : "r"(mbar), "r"(par) : "memory");
    if (!done) {
        asm volatile(
            "{\n\t"
            ".reg .pred P1;\n\t"
            "WL_%=:\n\t"
            "mbarrier.try_wait.parity.acquire.cluster.shared::cta.b64 P1, [%0], %1, 0x989680;\n\t"
            "@P1 bra.uni WD_%=;\n\t"
            "bra.uni WL_%=;\n\t"
            "WD_%=:\n\t"
            "}"
            :: "r"(mbar), "r"(par) : "memory");
    }
}
__device__ __forceinline__ void cluster_arrive_() {
    asm volatile("barrier.cluster.arrive.aligned;" ::: "memory");
}
__device__ __forceinline__ void cluster_wait_() {
    asm volatile("barrier.cluster.wait.aligned;" ::: "memory");
}

// One FFMA2 quad: 1 weight value against 8 batches (4 f32x2 pairs)
#define QFMA(ar, wv, sA, sB)                 \
    do {                                      \
        ull _w = pack2(wv);                   \
        fma2(ar##0, _w, sA.x);                \
        fma2(ar##1, _w, sA.y);                \
        fma2(ar##2, _w, sB.x);                \
        fma2(ar##3, _w, sB.y);                \
    } while (0)

extern "C" __global__ void __cluster_dims__(NSL, 1, 1) __launch_bounds__(THREADS, 1)
rnn_step_kernel(const float* __restrict__ u,
                const float* __restrict__ Wrec,
                const float* __restrict__ Winp,
                const float* __restrict__ Wout,
                const float* __restrict__ y_init,
                const float* __restrict__ rnoise,
                const float* __restrict__ inoise,
                float* __restrict__ states,
                float* __restrict__ outs)
{
    extern __shared__ float sm[];
    float* s_sh = sm;                // [520][8] rows 0..511 state, 512..517 = u+inoise
    float* part = s_sh + F_SSH;      // [16 seg][64 n][12]
    const uint32_t mbar0 = smem_u32(part + F_PART);
    const uint32_t mbar1 = mbar0 + 8;

    const int tid  = threadIdx.x;
    const int ns   = blockIdx.x;     // cluster rank / n-slice
    const int bg   = blockIdx.y;     // batch group
    const int n0   = ns * ROWS;
    const int b0   = bg * BG;
    const int lane = tid & 31;
    const int wid  = tid >> 5;       // 0..7
    const int g    = lane & 15;      // row group: rows {2g,2g+1,2g+32,2g+33}
    const int h    = lane >> 4;      // k half within warp's 64-k segment
    const int seg  = wid * 2 + h;    // 0..15
    const int kb   = wid * 64 + h * 32;   // this thread's k base

    const int r0 = 2 * g, r1 = 2 * g + 1, r2 = 2 * g + 32, r3 = 2 * g + 33;

    // ---- W_rec slice into registers: 4 rows x 32 k = 32 float4 ----
    float4 wr0[8], wr1[8], wr2[8], wr3[8];
    {
        const float* p0 = Wrec + (size_t)(n0 + r0) * NN + kb;
        const float* p1 = Wrec + (size_t)(n0 + r1) * NN + kb;
        const float* p2 = Wrec + (size_t)(n0 + r2) * NN + kb;
        const float* p3 = Wrec + (size_t)(n0 + r3) * NN + kb;
        #pragma unroll
        for (int q = 0; q < 8; ++q) {
            wr0[q] = *(const float4*)(p0 + 4 * q);
            wr1[q] = *(const float4*)(p1 + 4 * q);
            wr2[q] = *(const float4*)(p2 + 4 * q);
            wr3[q] = *(const float4*)(p3 + 4 * q);
        }
    }
    // Input-term weights (k-row 512+seg), only segs 0..5 active
    float wi0 = 0.f, wi1 = 0.f, wi2 = 0.f, wi3 = 0.f;
    if (seg < NIN) {
        wi0 = Winp[(size_t)(n0 + r0) * NIN + seg];
        wi1 = Winp[(size_t)(n0 + r1) * NIN + seg];
        wi2 = Winp[(size_t)(n0 + r2) * NIN + seg];
        wi3 = Winp[(size_t)(n0 + r3) * NIN + seg];
    }

    // Reducer output assignments (2 outputs per thread)
    const int n_r0 = tid >> 3;            // 0..31
    const int n_r1 = (tid + 256) >> 3;    // 32..63
    const int b_r  = tid & 7;
    const float wo0a = Wout[n0 + n_r0];
    const float wo0b = Wout[n0 + n_r1];
    const float wo1a = Wout[NN + n0 + n_r0];
    const float wo1b = Wout[NN + n0 + n_r1];

    // x loader assignment (threads 0..47)
    const bool xload = (tid < NIN * BG);
    const int  xi = tid >> 3, xb = tid & 7;

    // ---- mbarrier init (before cluster sync so peers can't arrive early) ----
    if (tid == 0) {
        mbar_init(mbar0, MBAR_ARRIVALS);
        mbar_init(mbar1, MBAR_ARRIVALS);
    }

    // ---- Init state buffer + states[:,0,:] ----
    for (int idx = tid; idx < ROWS * BG; idx += THREADS) {
        int k = n0 + (idx >> 3);
        int b = idx & 7;
        float v = y_init[k];
        g_S[0][bg][k][b] = v;
        states[(size_t)k * TB + b0 + b] = v;
    }
    // ---- rank 0 zeroes this batch-group's output slab ----
    if (ns == 0) {
        for (int idx = tid; idx < NOUT * TS * BG; idx += THREADS) {
            int o   = idx / (TS * BG);          // 0 or 1 (stride 9600)
            int rem = idx - o * TS * BG;
            int t = rem >> 3;
            int b = rem & 7;
            outs[(size_t)o * TB + (size_t)t * NB + b0 + b] = 0.f;
        }
    }
    __syncthreads();
    cluster_arrive_();

    // ---- Prefetch t=0 streamed operands ----
    float x_v = 0.f, rn0, rn1;
    if (xload) {
        size_t off = (size_t)xi * TB + b0 + xb;
        x_v = __ldcs(u + off) + __ldcs(inoise + off);
    }
    rn0 = __ldcs(rnoise + (size_t)(n0 + n_r0) * TB + b0 + b_r);
    rn1 = __ldcs(rnoise + (size_t)(n0 + n_r1) * TB + b0 + b_r);

    cluster_wait_();   // g_S init + out zero + all mbar inits visible cluster-wide

    // ---- t = 0 outputs: Wout @ s0 ----
    {
        float s0v = y_init[n0 + n_r0];
        float s1v = y_init[n0 + n_r1];
        float v0 = wo0a * s0v + wo0b * s1v;
        float v1 = wo1a * s0v + wo1b * s1v;
        v0 += __shfl_xor_sync(0xffffffffu, v0, 8);
        v0 += __shfl_xor_sync(0xffffffffu, v0, 16);
        v1 += __shfl_xor_sync(0xffffffffu, v1, 8);
        v1 += __shfl_xor_sync(0xffffffffu, v1, 16);
        if (lane < 8) {
            atomicAdd(outs + b0 + lane, v0);
            atomicAdd(outs + TB + b0 + lane, v1);
        }
    }

    const float* sbase = s_sh + kb * BG;
    const float* sext  = s_sh + (NN + seg) * BG;

    int ph0 = 0, ph1 = 0;   // per-buffer wait parities (all threads track identically)

    for (int t = 0; t < TS - 1; ++t) {
        // ---- 1. stage full state (16KB) from L2 into s_sh ----
        const float4* Sp = (const float4*)(&g_S[t & 1][bg][0][0]);
        float4 v0 = __ldcg(Sp + tid);
        float4 v1 = __ldcg(Sp + tid + 256);
        float4 v2 = __ldcg(Sp + tid + 512);
        float4 v3 = __ldcg(Sp + tid + 768);
        float4* s4 = (float4*)s_sh;
        s4[tid]       = v0;
        s4[tid + 256] = v1;
        s4[tid + 512] = v2;
        s4[tid + 768] = v3;
        if (xload) s_sh[(NN + xi) * BG + xb] = x_v;
        __syncthreads();

        // ---- 2. GEMM partials: 32 k's (regs W) x 4 rows x 8 batches ----
        ull a00 = 0, a01 = 0, a02 = 0, a03 = 0;
        ull a10 = 0, a11 = 0, a12 = 0, a13 = 0;
        ull a20 = 0, a21 = 0, a22 = 0, a23 = 0;
        ull a30 = 0, a31 = 0, a32 = 0, a33 = 0;
        {
            const float* sp = sbase;
            #pragma unroll
            for (int q = 0; q < 8; ++q) {
                float4 w0q = wr0[q], w1q = wr1[q], w2q = wr2[q], w3q = wr3[q];
                #pragma unroll
                for (int c = 0; c < 4; ++c) {
                    ulonglong2 sA = *(const ulonglong2*)(sp);
                    ulonglong2 sB = *(const ulonglong2*)(sp + 4);
                    float w0v = (c == 0) ? w0q.x : (c == 1) ? w0q.y : (c == 2) ? w0q.z : w0q.w;
                    float w1v = (c == 0) ? w1q.x : (c == 1) ? w1q.y : (c == 2) ? w1q.z : w1q.w;
                    float w2v = (c == 0) ? w2q.x : (c == 1) ? w2q.y : (c == 2) ? w2q.z : w2q.w;
                    float w3v = (c == 0) ? w3q.x : (c == 1) ? w3q.y : (c == 2) ? w3q.z : w3q.w;
                    QFMA(a0, w0v, sA, sB);
                    QFMA(a1, w1v, sA, sB);
                    QFMA(a2, w2v, sA, sB);
                    QFMA(a3, w3v, sA, sB);
                    sp += BG;
                }
            }
            if (seg < NIN) {
                ulonglong2 sA = *(const ulonglong2*)(sext);
                ulonglong2 sB = *(const ulonglong2*)(sext + 4);
                QFMA(a0, wi0, sA, sB);
                QFMA(a1, wi1, sA, sB);
                QFMA(a2, wi2, sA, sB);
                QFMA(a3, wi3, sA, sB);
            }
        }
        // ---- 3. store partials ----
        {
            float4 q;
            float* pb = part + (seg * ROWS) * BP;
            unpack2(a00, q.x, q.y); unpack2(a01, q.z, q.w);
            *(float4*)(pb + r0 * BP) = q;
            unpack2(a02, q.x, q.y); unpack2(a03, q.z, q.w);
            *(float4*)(pb + r0 * BP + 4) = q;
            unpack2(a10, q.x, q.y); unpack2(a11, q.z, q.w);
            *(float4*)(pb + r1 * BP) = q;
            unpack2(a12, q.x, q.y); unpack2(a13, q.z, q.w);
            *(float4*)(pb + r1 * BP + 4) = q;
            unpack2(a20, q.x, q.y); unpack2(a21, q.z, q.w);
            *(float4*)(pb + r2 * BP) = q;
            unpack2(a22, q.x, q.y); unpack2(a23, q.z, q.w);
            *(float4*)(pb + r2 * BP + 4) = q;
            unpack2(a30, q.x, q.y); unpack2(a31, q.z, q.w);
            *(float4*)(pb + r3 * BP) = q;
            unpack2(a32, q.x, q.y); unpack2(a33, q.z, q.w);
            *(float4*)(pb + r3 * BP + 4) = q;
        }
        __syncthreads();

        // ---- 4. reduce, tanh, state update ----
        float ns0, ns1;
        {
            float pre0 = 0.f, pre1 = 0.f;
            #pragma unroll
            for (int sp = 0; sp < NSEG; ++sp) {
                pre0 += part[(sp * ROWS + n_r0) * BP + b_r];
                pre1 += part[(sp * ROWS + n_r1) * BP + b_r];
            }
            float s0 = s_sh[(n0 + n_r0) * BG + b_r];
            float s1 = s_sh[(n0 + n_r1) * BG + b_r];
            ns0 = 0.9f * s0 + 0.1f * (tanh_fast(pre0) + rn0);
            ns1 = 0.9f * s1 + 0.1f * (tanh_fast(pre1) + rn1);
            float* Sn = &g_S[(t + 1) & 1][bg][0][0];
            Sn[(n0 + n_r0) * BG + b_r] = ns0;   // ONLY g_S before the release
            Sn[(n0 + n_r1) * BG + b_r] = ns1;
        }

        // ---- 5. signal: per-warp release + arrive on all 8 cluster mbars ----
        const uint32_t mb = ((t + 1) & 1) ? mbar1 : mbar0;
        __syncwarp();
        if (lane == 0) {
            fence_cluster_();                 // make this warp's g_S writes cluster-visible
            #pragma unroll
            for (int r = 0; r < NSL; ++r)
                mbar_arrive_rank(mb, r);
        }

        // ---- 6. off-chain work: states STG, outs RED, next prefetch ----
        {
            size_t so = (size_t)(t + 1) * NB + b0 + b_r;
            states[(size_t)(n0 + n_r0) * TB + so] = ns0;
            states[(size_t)(n0 + n_r1) * TB + so] = ns1;

            float v0 = wo0a * ns0 + wo0b * ns1;
            float v1 = wo1a * ns0 + wo1b * ns1;
            v0 += __shfl_xor_sync(0xffffffffu, v0, 8);
            v0 += __shfl_xor_sync(0xffffffffu, v0, 16);
            v1 += __shfl_xor_sync(0xffffffffu, v1, 8);
            v1 += __shfl_xor_sync(0xffffffffu, v1, 16);
            if (lane < 8) {
                size_t oc = (size_t)(t + 1) * NB + b0 + lane;
                atomicAdd(outs + oc, v0);
                atomicAdd(outs + TB + oc, v1);
            }
        }
        if (t + 1 < TS - 1) {
            size_t toff = (size_t)(t + 1) * NB + b0;
            if (xload) {
                size_t off = (size_t)xi * TB + toff + xb;
                x_v = __ldcs(u + off) + __ldcs(inoise + off);
            }
            rn0 = __ldcs(rnoise + (size_t)(n0 + n_r0) * TB + toff + b_r);
            rn1 = __ldcs(rnoise + (size_t)(n0 + n_r1) * TB + toff + b_r);
        }

        // ---- 7. wait for the cluster-wide exchange of step t+1 ----
        if ((t + 1) & 1) {
            mbar_wait_cluster(mbar1, ph1);
            ph1 ^= 1;
        } else {
            mbar_wait_cluster(mbar0, ph0);
            ph0 ^= 1;
        }
    }
}

extern "C" void kernel_launch(void* const* d_in, const int* in_sizes, int n_in,
                              void* d_out, int out_size)
{
    const float* u      = (const float*)d_in[0];
    const float* Wrec   = (const float*)d_in[1];
    const float* Winp   = (const float*)d_in[2];
    const float* Wout   = (const float*)d_in[3];
    const float* y_init = (const float*)d_in[4];
    const float* rnoise = (const float*)d_in[5];
    const float* inoise = (const float*)d_in[6];

    float* states = (float*)d_out;
    float* outs   = states + (size_t)NN * TB;

    cudaFuncSetAttribute(rnn_step_kernel,
                         cudaFuncAttributeMaxDynamicSharedMemorySize, SMEM_BYTES);

    dim3 grid(NSL, NBG, 1);
    rnn_step_kernel<<<grid, THREADS, SMEM_BYTES>>>(u, Wrec, Winp, Wout, y_init,
                                                   rnoise, inoise, states, outs);
}

// round 10
// speedup vs baseline: 1.1154x; 1.0283x over previous
#include <cuda_runtime.h>
#include <cstdint>

// Problem constants
#define NN   512
#define NIN  6
#define NOUT 2
#define TS   1200
#define NB   128
#define TB   (TS * NB)          // 153600

// Decomposition: 16 batch-groups x (cluster of 8 n-slice CTAs) = 128 CTAs
#define NSL     8               // n-slices (cluster size)
#define ROWS    64              // rows of W_rec per CTA
#define NBG     16              // batch groups
#define BG      8               // batch per group
#define THREADS 256
#define NSEG    16              // k-segments (8 warps x 2 half-warps)
#define BP      12              // partials row pad (floats, mult of 4 for STS.128)

#define F_SSH   ((NN + NIN + 2) * BG)   // 4160: 512 state rows + 6 input rows + pad
#define F_PART  (NSEG * ROWS * BP)      // 12288
#define F_MBAR  4                       // 2 x 8-byte mbarriers
#define SMEM_FLOATS (F_SSH + F_PART + F_MBAR)
#define SMEM_BYTES  (SMEM_FLOATS * 4)   // 65808 B

#define MBAR_ARRIVALS NSL               // ONE aggregated arrive per source CTA

// Ping-pong state exchange buffer (per batch-group), lives in L2.
__device__ float g_S[2][NBG][NN][BG];

typedef unsigned long long ull;

__device__ __forceinline__ ull pack2(float x) {
    ull r;
    unsigned int v = __float_as_uint(x);
    asm("mov.b64 %0, {%1, %1};" : "=l"(r) : "r"(v));
    return r;
}
__device__ __forceinline__ void fma2(ull& d, ull a, ull b) {
    asm("fma.rn.f32x2 %0, %1, %2, %0;" : "+l"(d) : "l"(a), "l"(b));
}
__device__ __forceinline__ void unpack2(ull v, float& lo, float& hi) {
    unsigned int l, h;
    asm("mov.b64 {%0, %1}, %2;" : "=r"(l), "=r"(h) : "l"(v));
    lo = __uint_as_float(l);
    hi = __uint_as_float(h);
}
__device__ __forceinline__ float tanh_fast(float x) {
    float r;
    asm("tanh.approx.f32 %0, %1;" : "=f"(r) : "f"(x));
    return r;
}
__device__ __forceinline__ uint32_t smem_u32(const void* p) {
    uint32_t a;
    asm("{ .reg .u64 t; cvta.to.shared.u64 t, %1; cvt.u32.u64 %0, t; }"
        : "=r"(a) : "l"(p));
    return a;
}
__device__ __forceinline__ void mbar_init(uint32_t addr, uint32_t cnt) {
    asm volatile("mbarrier.init.shared.b64 [%0], %1;" :: "r"(addr), "r"(cnt) : "memory");
}
__device__ __forceinline__ void fence_cluster_() {
    asm volatile("fence.acq_rel.cluster;" ::: "memory");
}
// Arrive on cluster CTA `rank`'s mbarrier at the same smem offset.
__device__ __forceinline__ void mbar_arrive_rank(uint32_t addr, uint32_t rank) {
    asm volatile(
        "{\n\t"
        ".reg .b32 ra;\n\t"
        "mapa.shared::cluster.u32 ra, %0, %1;\n\t"
        "mbarrier.arrive.shared::cluster.b64 _, [ra];\n\t"
        "}"
        :: "r"(addr), "r"(rank) : "memory");
}
// Spin-wait on local mbarrier phase parity with cluster-scope acquire.
__device__ __forceinline__ void mbar_wait_cluster(uint32_t mbar, uint32_t par) {
    uint32_t done;
    asm volatile(
        "{\n\t"
        ".reg .pred p;\n\t"
        "mbarrier.try_wait.parity.acquire.cluster.shared::cta.b64 p, [%1], %2;\n\t"
        "selp.b32 %0, 1, 0, p;\n\t"
        "}"
        : "=r"(done) : "r"(mbar), "r"(par) : "memory");
    if (!done) {
        asm volatile(
            "{\n\t"
            ".reg .pred P1;\n\t"
            "WL_%=:\n\t"
            "mbarrier.try_wait.parity.acquire.cluster.shared::cta.b64 P1, [%0], %1, 0x989680;\n\t"
            "@P1 bra.uni WD_%=;\n\t"
            "bra.uni WL_%=;\n\t"
            "WD_%=:\n\t"
            "}"
            :: "r"(mbar), "r"(par) : "memory");
    }
}
__device__ __forceinline__ void cluster_arrive_() {
    asm volatile("barrier.cluster.arrive.aligned;" ::: "memory");
}
__device__ __forceinline__ void cluster_wait_() {
    asm volatile("barrier.cluster.wait.aligned;" ::: "memory");
}

// One FFMA2 quad: 1 weight value against 8 batches (4 f32x2 pairs)
#define QFMA(ar, wv, sA, sB)                 \
    do {                                      \
        ull _w = pack2(wv);                   \
        fma2(ar##0, _w, sA.x);                \
        fma2(ar##1, _w, sA.y);                \
        fma2(ar##2, _w, sB.x);                \
        fma2(ar##3, _w, sB.y);                \
    } while (0)

extern "C" __global__ void __cluster_dims__(NSL, 1, 1) __launch_bounds__(THREADS, 1)
rnn_step_kernel(const float* __restrict__ u,
                const float* __restrict__ Wrec,
                const float* __restrict__ Winp,
                const float* __restrict__ Wout,
                const float* __restrict__ y_init,
                const float* __restrict__ rnoise,
                const float* __restrict__ inoise,
                float* __restrict__ states,
                float* __restrict__ outs)
{
    extern __shared__ float sm[];
    float* s_sh = sm;                // [520][8] rows 0..511 state, 512..517 = u+inoise
    float* part = s_sh + F_SSH;      // [16 seg][64 n][12]
    const uint32_t mbar0 = smem_u32(part + F_PART);
    const uint32_t mbar1 = mbar0 + 8;

    const int tid  = threadIdx.x;
    const int ns   = blockIdx.x;     // cluster rank / n-slice
    const int bg   = blockIdx.y;     // batch group
    const int n0   = ns * ROWS;
    const int b0   = bg * BG;
    const int lane = tid & 31;
    const int wid  = tid >> 5;       // 0..7
    const int g    = lane & 15;      // row group: rows {2g,2g+1,2g+32,2g+33}
    const int h    = lane >> 4;      // k half within warp's 64-k segment
    const int seg  = wid * 2 + h;    // 0..15
    const int kb   = wid * 64 + h * 32;   // this thread's k base

    const int r0 = 2 * g, r1 = 2 * g + 1, r2 = 2 * g + 32, r3 = 2 * g + 33;

    // ---- W_rec slice into registers: 4 rows x 32 k = 32 float4 ----
    float4 wr0[8], wr1[8], wr2[8], wr3[8];
    {
        const float* p0 = Wrec + (size_t)(n0 + r0) * NN + kb;
        const float* p1 = Wrec + (size_t)(n0 + r1) * NN + kb;
        const float* p2 = Wrec + (size_t)(n0 + r2) * NN + kb;
        const float* p3 = Wrec + (size_t)(n0 + r3) * NN + kb;
        #pragma unroll
        for (int q = 0; q < 8; ++q) {
            wr0[q] = *(const float4*)(p0 + 4 * q);
            wr1[q] = *(const float4*)(p1 + 4 * q);
            wr2[q] = *(const float4*)(p2 + 4 * q);
            wr3[q] = *(const float4*)(p3 + 4 * q);
        }
    }
    // Input-term weights (k-row 512+seg), only segs 0..5 active
    float wi0 = 0.f, wi1 = 0.f, wi2 = 0.f, wi3 = 0.f;
    if (seg < NIN) {
        wi0 = Winp[(size_t)(n0 + r0) * NIN + seg];
        wi1 = Winp[(size_t)(n0 + r1) * NIN + seg];
        wi2 = Winp[(size_t)(n0 + r2) * NIN + seg];
        wi3 = Winp[(size_t)(n0 + r3) * NIN + seg];
    }

    // Reducer output assignments (2 outputs per thread)
    const int n_r0 = tid >> 3;            // 0..31
    const int n_r1 = (tid + 256) >> 3;    // 32..63
    const int b_r  = tid & 7;
    const float wo0a = Wout[n0 + n_r0];
    const float wo0b = Wout[n0 + n_r1];
    const float wo1a = Wout[NN + n0 + n_r0];
    const float wo1b = Wout[NN + n0 + n_r1];

    // x loader assignment (threads 0..47)
    const bool xload = (tid < NIN * BG);
    const int  xi = tid >> 3, xb = tid & 7;

    // ---- mbarrier init (before cluster sync so peers can't arrive early) ----
    if (tid == 0) {
        mbar_init(mbar0, MBAR_ARRIVALS);
        mbar_init(mbar1, MBAR_ARRIVALS);
    }

    // ---- Init state buffer + states[:,0,:] + own rows of s_sh ----
    for (int idx = tid; idx < ROWS * BG; idx += THREADS) {
        int n = idx >> 3;
        int b = idx & 7;
        float v = y_init[n0 + n];
        g_S[0][bg][n0 + n][b] = v;
        s_sh[(n0 + n) * BG + b] = v;    // own slice seeded locally (stage skips it)
        states[(size_t)(n0 + n) * TB + b0 + b] = v;
    }
    // ---- rank 0 zeroes this batch-group's output slab ----
    if (ns == 0) {
        for (int idx = tid; idx < NOUT * TS * BG; idx += THREADS) {
            int o   = idx / (TS * BG);          // 0 or 1 (stride 9600)
            int rem = idx - o * TS * BG;
            int t = rem >> 3;
            int b = rem & 7;
            outs[(size_t)o * TB + (size_t)t * NB + b0 + b] = 0.f;
        }
    }
    __syncthreads();
    cluster_arrive_();

    // ---- Prefetch t=0 streamed operands ----
    float x_v = 0.f, rn0, rn1;
    if (xload) {
        size_t off = (size_t)xi * TB + b0 + xb;
        x_v = __ldcs(u + off) + __ldcs(inoise + off);
    }
    rn0 = __ldcs(rnoise + (size_t)(n0 + n_r0) * TB + b0 + b_r);
    rn1 = __ldcs(rnoise + (size_t)(n0 + n_r1) * TB + b0 + b_r);

    cluster_wait_();   // g_S init + out zero + all mbar inits visible cluster-wide

    // ---- t = 0 outputs: Wout @ s0 ----
    {
        float s0v = y_init[n0 + n_r0];
        float s1v = y_init[n0 + n_r1];
        float v0 = wo0a * s0v + wo0b * s1v;
        float v1 = wo1a * s0v + wo1b * s1v;
        v0 += __shfl_xor_sync(0xffffffffu, v0, 8);
        v0 += __shfl_xor_sync(0xffffffffu, v0, 16);
        v1 += __shfl_xor_sync(0xffffffffu, v1, 8);
        v1 += __shfl_xor_sync(0xffffffffu, v1, 16);
        if (lane < 8) {
            atomicAdd(outs + b0 + lane, v0);
            atomicAdd(outs + TB + b0 + lane, v1);
        }
    }

    const float* sbase = s_sh + kb * BG;
    const float* sext  = s_sh + (NN + seg) * BG;

    int ph0 = 0, ph1 = 0;   // per-buffer wait parities

    for (int t = 0; t < TS - 1; ++t) {
        // ---- 1. stage remote slices (14KB) from L2; own slice already local ----
        const float4* Sp = (const float4*)(&g_S[t & 1][bg][0][0]);
        float4* s4 = (float4*)s_sh;
        #pragma unroll
        for (int j = 0; j < 4; ++j) {
            int idx = tid + j * 256;        // 0..1023 float4s; slice = idx>>7
            if ((idx >> 7) != ns)
                s4[idx] = __ldcg(Sp + idx);
        }
        if (xload) s_sh[(NN + xi) * BG + xb] = x_v;
        __syncthreads();

        // ---- 2. GEMM partials: 32 k's (regs W) x 4 rows x 8 batches ----
        ull a00 = 0, a01 = 0, a02 = 0, a03 = 0;
        ull a10 = 0, a11 = 0, a12 = 0, a13 = 0;
        ull a20 = 0, a21 = 0, a22 = 0, a23 = 0;
        ull a30 = 0, a31 = 0, a32 = 0, a33 = 0;
        {
            const float* sp = sbase;
            #pragma unroll
            for (int q = 0; q < 8; ++q) {
                float4 w0q = wr0[q], w1q = wr1[q], w2q = wr2[q], w3q = wr3[q];
                #pragma unroll
                for (int c = 0; c < 4; ++c) {
                    ulonglong2 sA = *(const ulonglong2*)(sp);
                    ulonglong2 sB = *(const ulonglong2*)(sp + 4);
                    float w0v = (c == 0) ? w0q.x : (c == 1) ? w0q.y : (c == 2) ? w0q.z : w0q.w;
                    float w1v = (c == 0) ? w1q.x : (c == 1) ? w1q.y : (c == 2) ? w1q.z : w1q.w;
                    float w2v = (c == 0) ? w2q.x : (c == 1) ? w2q.y : (c == 2) ? w2q.z : w2q.w;
                    float w3v = (c == 0) ? w3q.x : (c == 1) ? w3q.y : (c == 2) ? w3q.z : w3q.w;
                    QFMA(a0, w0v, sA, sB);
                    QFMA(a1, w1v, sA, sB);
                    QFMA(a2, w2v, sA, sB);
                    QFMA(a3, w3v, sA, sB);
                    sp += BG;
                }
            }
            if (seg < NIN) {
                ulonglong2 sA = *(const ulonglong2*)(sext);
                ulonglong2 sB = *(const ulonglong2*)(sext + 4);
                QFMA(a0, wi0, sA, sB);
                QFMA(a1, wi1, sA, sB);
                QFMA(a2, wi2, sA, sB);
                QFMA(a3, wi3, sA, sB);
            }
        }
        // ---- 3. store partials ----
        {
            float4 q;
            float* pb = part + (seg * ROWS) * BP;
            unpack2(a00, q.x, q.y); unpack2(a01, q.z, q.w);
            *(float4*)(pb + r0 * BP) = q;
            unpack2(a02, q.x, q.y); unpack2(a03, q.z, q.w);
            *(float4*)(pb + r0 * BP + 4) = q;
            unpack2(a10, q.x, q.y); unpack2(a11, q.z, q.w);
            *(float4*)(pb + r1 * BP) = q;
            unpack2(a12, q.x, q.y); unpack2(a13, q.z, q.w);
            *(float4*)(pb + r1 * BP + 4) = q;
            unpack2(a20, q.x, q.y); unpack2(a21, q.z, q.w);
            *(float4*)(pb + r2 * BP) = q;
            unpack2(a22, q.x, q.y); unpack2(a23, q.z, q.w);
            *(float4*)(pb + r2 * BP + 4) = q;
            unpack2(a30, q.x, q.y); unpack2(a31, q.z, q.w);
            *(float4*)(pb + r3 * BP) = q;
            unpack2(a32, q.x, q.y); unpack2(a33, q.z, q.w);
            *(float4*)(pb + r3 * BP + 4) = q;
        }
        __syncthreads();

        // ---- 4. reduce, tanh, state update (g_S STG + local s_sh STS) ----
        float ns0, ns1;
        {
            float pre0 = 0.f, pre1 = 0.f;
            #pragma unroll
            for (int sp = 0; sp < NSEG; ++sp) {
                pre0 += part[(sp * ROWS + n_r0) * BP + b_r];
                pre1 += part[(sp * ROWS + n_r1) * BP + b_r];
            }
            float s0 = s_sh[(n0 + n_r0) * BG + b_r];
            float s1 = s_sh[(n0 + n_r1) * BG + b_r];
            ns0 = 0.9f * s0 + 0.1f * (tanh_fast(pre0) + rn0);
            ns1 = 0.9f * s1 + 0.1f * (tanh_fast(pre1) + rn1);
            float* Sn = &g_S[(t + 1) & 1][bg][0][0];
            Sn[(n0 + n_r0) * BG + b_r] = ns0;       // remote CTAs read via L2
            Sn[(n0 + n_r1) * BG + b_r] = ns1;
            s_sh[(n0 + n_r0) * BG + b_r] = ns0;     // own slice stays local
            s_sh[(n0 + n_r1) * BG + b_r] = ns1;
        }

        // ---- 5. aggregated signal: 1 arrive per source CTA per rank ----
        const uint32_t mb = ((t + 1) & 1) ? mbar1 : mbar0;
        __syncthreads();                    // all g_S STGs issued before fence
        if (tid < NSL) {
            fence_cluster_();               // cluster-visible release of g_S writes
            mbar_arrive_rank(mb, tid);      // 8 parallel arrives, one per rank
        }

        // ---- 6. off-chain work: states STG, outs RED, next prefetch ----
        {
            size_t so = (size_t)(t + 1) * NB + b0 + b_r;
            states[(size_t)(n0 + n_r0) * TB + so] = ns0;
            states[(size_t)(n0 + n_r1) * TB + so] = ns1;

            float v0 = wo0a * ns0 + wo0b * ns1;
            float v1 = wo1a * ns0 + wo1b * ns1;
            v0 += __shfl_xor_sync(0xffffffffu, v0, 8);
            v0 += __shfl_xor_sync(0xffffffffu, v0, 16);
            v1 += __shfl_xor_sync(0xffffffffu, v1, 8);
            v1 += __shfl_xor_sync(0xffffffffu, v1, 16);
            if (lane < 8) {
                size_t oc = (size_t)(t + 1) * NB + b0 + lane;
                atomicAdd(outs + oc, v0);
                atomicAdd(outs + TB + oc, v1);
            }
        }
        if (t + 1 < TS - 1) {
            size_t toff = (size_t)(t + 1) * NB + b0;
            if (xload) {
                size_t off = (size_t)xi * TB + toff + xb;
                x_v = __ldcs(u + off) + __ldcs(inoise + off);
            }
            rn0 = __ldcs(rnoise + (size_t)(n0 + n_r0) * TB + toff + b_r);
            rn1 = __ldcs(rnoise + (size_t)(n0 + n_r1) * TB + toff + b_r);
        }

        // ---- 7. wait for the cluster-wide exchange of step t+1 ----
        if ((t + 1) & 1) {
            mbar_wait_cluster(mbar1, ph1);
            ph1 ^= 1;
        } else {
            mbar_wait_cluster(mbar0, ph0);
            ph0 ^= 1;
        }
    }
}

extern "C" void kernel_launch(void* const* d_in, const int* in_sizes, int n_in,
                              void* d_out, int out_size)
{
    const float* u      = (const float*)d_in[0];
    const float* Wrec   = (const float*)d_in[1];
    const float* Winp   = (const float*)d_in[2];
    const float* Wout   = (const float*)d_in[3];
    const float* y_init = (const float*)d_in[4];
    const float* rnoise = (const float*)d_in[5];
    const float* inoise = (const float*)d_in[6];

    float* states = (float*)d_out;
    float* outs   = states + (size_t)NN * TB;

    cudaFuncSetAttribute(rnn_step_kernel,
                         cudaFuncAttributeMaxDynamicSharedMemorySize, SMEM_BYTES);

    dim3 grid(NSL, NBG, 1);
    rnn_step_kernel<<<grid, THREADS, SMEM_BYTES>>>(u, Wrec, Winp, Wout, y_init,
                                                   rnoise, inoise, states, outs);
}